// round 9
// baseline (speedup 1.0000x reference)
#include <cuda_runtime.h>
#include <cuda_bf16.h>
#include <cstdint>

#define XDIM 128
#define X3   (XDIM * XDIM * XDIM)   // 2,097,152 voxels
#define NB   16                     // batch
#define ZBLOCKS 489                  // zero kernel work blocks (4 idx/thread)
#define ZT   (ZBLOCKS * 256)         // zero stride

// Grid in bf16, batch-minor: g_grid[v*NB + b]. 64 MiB, zero-init at load.
// INVARIANT: all-zero at entry to every kernel_launch. Order per launch:
// scatter -> reduce -> zero(touched)+finalize. Zeroing the touched set at the
// END restores the invariant for the next graph replay.
__device__ __nv_bfloat16 g_grid[(size_t)X3 * NB];
__device__ double g_acc[2 * NB];   // [0..15] tv sums, [16..31] mse sums

// ---------------------------------------------------------------------------
// Scatter: one thread per index; 2 x red.global.add.v4.bf16x2 (16 batches).
// ---------------------------------------------------------------------------
__global__ void scatter_kernel(const int* __restrict__ idx,
                               const float* __restrict__ vals, int N) {
    int n = blockIdx.x * blockDim.x + threadIdx.x;
    if (n >= N) return;
    int z = __ldcs(idx + 3 * n + 0);
    int y = __ldcs(idx + 3 * n + 1);
    int x = __ldcs(idx + 3 * n + 2);
    size_t v = (size_t)(((z << 7) + y) * XDIM + x);

    unsigned w[8];
#pragma unroll
    for (int g = 0; g < 8; g++) {
        float a = __ldcs(vals + (size_t)(2 * g) * N + n);
        float b = __ldcs(vals + (size_t)(2 * g + 1) * N + n);
        __nv_bfloat162 p = __floats2bfloat162_rn(a, b);
        w[g] = *reinterpret_cast<unsigned*>(&p);
    }

    __nv_bfloat16* base = g_grid + v * NB;
    asm volatile("red.global.add.noftz.v4.bf16x2 [%0], {%1, %2, %3, %4};"
                 :: "l"(base), "r"(w[0]), "r"(w[1]), "r"(w[2]), "r"(w[3])
                 : "memory");
    asm volatile("red.global.add.noftz.v4.bf16x2 [%0], {%1, %2, %3, %4};"
                 :: "l"(base + 8), "r"(w[4]), "r"(w[5]), "r"(w[6]), "r"(w[7])
                 : "memory");
}

// ---------------------------------------------------------------------------
// Packed diff-accumulate (see r4): HADD2 diff, shl/and unpack, FADD |.| TV,
// packed fma.rn.f32x2 MSE.
// ---------------------------------------------------------------------------
#define ACCW(sw, nw, k, mp) do {                                              \
    __nv_bfloat162 _a = *reinterpret_cast<const __nv_bfloat162*>(&(nw));      \
    __nv_bfloat162 _b = *reinterpret_cast<const __nv_bfloat162*>(&(sw));      \
    __nv_bfloat162 _d = __hsub2(_a, _b);                                      \
    unsigned _du = *reinterpret_cast<unsigned*>(&_d);                         \
    float _lo = __uint_as_float(_du << 16);                                   \
    float _hi = __uint_as_float(_du & 0xffff0000u);                           \
    tv[(k)]     += fabsf(_lo);                                                \
    tv[(k) + 1] += fabsf(_hi);                                                \
    unsigned long long _dp;                                                   \
    asm("mov.b64 %0, {%1, %2};" : "=l"(_dp)                                   \
        : "r"(__float_as_uint(_lo)), "r"(__float_as_uint(_hi)));              \
    asm("fma.rn.f32x2 %0, %1, %2, %3;" : "=l"(mp)                             \
        : "l"(_dp), "l"(_dp), "l"(mp));                                       \
} while (0)

#define ACC4(s, nb) do {                                                      \
    ACCW((s).x, (nb).x, 0, msep[0]);                                          \
    ACCW((s).y, (nb).y, 2, msep[1]);                                          \
    ACCW((s).z, (nb).z, 4, msep[2]);                                          \
    ACCW((s).w, (nb).w, 6, msep[3]);                                          \
} while (0)

// ---------------------------------------------------------------------------
// Reduce: block = one z-plane slice (8 y rows), grid = 16 y-octets x 128 z.
// 2048 blocks -> 4+ waves, work-steal balanced. Warp = one y row: 512B
// contiguous loads; x+1 direct (+2, L1 hit), y+1 via sibling warps (L1),
// z+1 from the next block's plane (L2 hit). No launch_bounds: let ptxas
// pipeline the unrolled chunks with a bigger register budget.
// ---------------------------------------------------------------------------
__global__ void reduce_kernel() {
    const uint4* __restrict__ g4 = (const uint4*)g_grid;
    int tid  = threadIdx.x;
    int lane = tid & 31;
    int wrp  = tid >> 5;             // 0..7
    int bg   = lane & 1;
    int xl   = lane >> 1;            // 0..15
    int y    = blockIdx.x * 8 + wrp; // 0..127
    int z    = blockIdx.y;           // 0..127
    bool yok = (y < XDIM - 1);
    bool zok = (z < XDIM - 1);

    float tv[8];
    unsigned long long msep[4];
#pragma unroll
    for (int i = 0; i < 8; i++) tv[i] = 0.f;
#pragma unroll
    for (int i = 0; i < 4; i++) msep[i] = 0ull;

    size_t row2 = ((size_t)(z << 7) + y) * (XDIM * 2);   // uint4 idx at x=0

#pragma unroll
    for (int c = 0; c < 8; c++) {
        size_t i0 = row2 + c * 32 + lane;
        uint4 s = g4[i0];

        if (c < 7) {
            uint4 nx = g4[i0 + 2];
            ACC4(s, nx);
        } else if (xl < 15) {                  // x = 112..126 only
            uint4 nx = g4[i0 + 2];
            ACC4(s, nx);
        }
        if (yok) { uint4 ny = g4[i0 + 2 * XDIM];        ACC4(s, ny); }
        if (zok) { uint4 nz = g4[i0 + 2 * XDIM * XDIM]; ACC4(s, nz); }
    }

    // Unpack packed mse pairs.
    float mse[8];
#pragma unroll
    for (int i = 0; i < 4; i++) {
        unsigned _lo, _hi;
        asm("mov.b64 {%0, %1}, %2;" : "=r"(_lo), "=r"(_hi) : "l"(msep[i]));
        mse[2 * i]     = __uint_as_float(_lo);
        mse[2 * i + 1] = __uint_as_float(_hi);
    }

    // Warp reduce over lanes sharing bg (stride-2 lanes): xor 2,4,8,16.
#pragma unroll
    for (int off = 2; off <= 16; off <<= 1) {
#pragma unroll
        for (int i = 0; i < 8; i++) {
            tv[i]  += __shfl_xor_sync(0xffffffffu, tv[i],  off);
            mse[i] += __shfl_xor_sync(0xffffffffu, mse[i], off);
        }
    }

    __shared__ float s_tv[NB], s_mse[NB];
    if (tid < NB) { s_tv[tid] = 0.f; s_mse[tid] = 0.f; }
    __syncthreads();

    if (lane < 2) {                  // lane 0 = bg0 totals, lane 1 = bg1
#pragma unroll
        for (int i = 0; i < 8; i++) {
            atomicAdd(&s_tv[bg * 8 + i],  tv[i]);
            atomicAdd(&s_mse[bg * 8 + i], mse[i]);
        }
    }
    __syncthreads();

    if (tid < NB) {
        atomicAdd(&g_acc[tid],      (double)s_tv[tid]);
        atomicAdd(&g_acc[NB + tid], (double)s_mse[tid]);
    }
}

// ---------------------------------------------------------------------------
// Zero the touched voxels (4 indices per thread, batched for MLP); last block
// finalizes (normalize g_acc -> out, reset for next replay).
// ---------------------------------------------------------------------------
__global__ void zero_fin_kernel(const int* __restrict__ idx, int N,
                                float* __restrict__ out) {
    if (blockIdx.x == gridDim.x - 1) {
        int t = threadIdx.x;
        if (t < 32) {
            double norm = (t < NB) ? (double)X3
                                   : (double)(2 * XDIM * XDIM - 2 * XDIM);
            out[t] = (float)(g_acc[t] / norm);
            g_acc[t] = 0.0;          // restore invariant for next replay
        }
        return;
    }
    int g = blockIdx.x * blockDim.x + threadIdx.x;
    const int n0 = g, n1 = g + ZT, n2 = g + 2 * ZT, n3 = g + 3 * ZT;
    const bool k0 = n0 < N, k1 = n1 < N, k2 = n2 < N, k3 = n3 < N;

    size_t v0 = 0, v1 = 0, v2 = 0, v3 = 0;
    if (k0) { int z = __ldcs(idx + 3 * n0), y = __ldcs(idx + 3 * n0 + 1),
                  x = __ldcs(idx + 3 * n0 + 2);
              v0 = (size_t)(((z << 7) + y) * XDIM + x); }
    if (k1) { int z = __ldcs(idx + 3 * n1), y = __ldcs(idx + 3 * n1 + 1),
                  x = __ldcs(idx + 3 * n1 + 2);
              v1 = (size_t)(((z << 7) + y) * XDIM + x); }
    if (k2) { int z = __ldcs(idx + 3 * n2), y = __ldcs(idx + 3 * n2 + 1),
                  x = __ldcs(idx + 3 * n2 + 2);
              v2 = (size_t)(((z << 7) + y) * XDIM + x); }
    if (k3) { int z = __ldcs(idx + 3 * n3), y = __ldcs(idx + 3 * n3 + 1),
                  x = __ldcs(idx + 3 * n3 + 2);
              v3 = (size_t)(((z << 7) + y) * XDIM + x); }

    uint4 z4 = make_uint4(0u, 0u, 0u, 0u);
    if (k0) { uint4* p = (uint4*)(g_grid + v0 * NB); p[0] = z4; p[1] = z4; }
    if (k1) { uint4* p = (uint4*)(g_grid + v1 * NB); p[0] = z4; p[1] = z4; }
    if (k2) { uint4* p = (uint4*)(g_grid + v2 * NB); p[0] = z4; p[1] = z4; }
    if (k3) { uint4* p = (uint4*)(g_grid + v3 * NB); p[0] = z4; p[1] = z4; }
}

extern "C" void kernel_launch(void* const* d_in, const int* in_sizes, int n_in,
                              void* d_out, int out_size) {
    const int*   indices = (const int*)d_in[0];
    const float* values  = (const float*)d_in[1];
    int N = in_sizes[0] / 3;        // 500000

    scatter_kernel<<<(N + 255) / 256, 256>>>(indices, values, N);
    reduce_kernel<<<dim3(16, 128), 256>>>();
    zero_fin_kernel<<<ZBLOCKS + 1, 256>>>(indices, N, (float*)d_out);
}

// round 10
// speedup vs baseline: 1.1580x; 1.1580x over previous
#include <cuda_runtime.h>
#include <cuda_bf16.h>
#include <cstdint>

#define XDIM 128
#define X3   (XDIM * XDIM * XDIM)   // 2,097,152 voxels
#define NB   16                     // batch

// Grid in bf16, batch-minor: g_grid[v*NB + b]. 64 MiB, zero-init at load.
// INVARIANT: all-zero at entry to every kernel_launch. Order per launch:
// scatter -> reduce -> zero(touched)+finalize (restores invariant).
__device__ __nv_bfloat16 g_grid[(size_t)X3 * NB];
__device__ double g_acc[2 * NB];   // [0..15] tv sums, [16..31] mse sums

// ---------------------------------------------------------------------------
// Scatter: one thread per PAIR of consecutive indices (n, n+1).
// Value loads become float2 (contiguous along n): 16 LDG.64 per 2 indices
// instead of 32 LDG.32. Index loads: 3 x int2 (8B-aligned since n is even).
// ---------------------------------------------------------------------------
__global__ void scatter_kernel(const int* __restrict__ idx,
                               const float* __restrict__ vals, int N) {
    int t = blockIdx.x * blockDim.x + threadIdx.x;
    int n = 2 * t;
    if (n >= N) return;
    bool has2 = (n + 1 < N);

    const int2* ip = (const int2*)(idx + 3 * n);   // 12n bytes, n even -> 8B ok
    int2 p0 = __ldcs(ip + 0);
    int2 p1 = __ldcs(ip + 1);
    int2 p2 = __ldcs(ip + 2);
    size_t v0 = (size_t)(((p0.x << 7) + p0.y) * XDIM + p1.x);
    size_t v1 = (size_t)(((p1.y << 7) + p2.x) * XDIM + p2.y);

    unsigned w0[8], w1[8];
#pragma unroll
    for (int g = 0; g < 8; g++) {
        const float2* ap = (const float2*)(vals + (size_t)(2 * g) * N + n);
        const float2* bp = (const float2*)(vals + (size_t)(2 * g + 1) * N + n);
        float2 a = __ldcs(ap);       // batches 2g   for n, n+1
        float2 b = __ldcs(bp);       // batches 2g+1 for n, n+1
        __nv_bfloat162 q0 = __floats2bfloat162_rn(a.x, b.x);
        __nv_bfloat162 q1 = __floats2bfloat162_rn(a.y, b.y);
        w0[g] = *reinterpret_cast<unsigned*>(&q0);
        w1[g] = *reinterpret_cast<unsigned*>(&q1);
    }

    __nv_bfloat16* b0 = g_grid + v0 * NB;
    asm volatile("red.global.add.noftz.v4.bf16x2 [%0], {%1, %2, %3, %4};"
                 :: "l"(b0), "r"(w0[0]), "r"(w0[1]), "r"(w0[2]), "r"(w0[3])
                 : "memory");
    asm volatile("red.global.add.noftz.v4.bf16x2 [%0], {%1, %2, %3, %4};"
                 :: "l"(b0 + 8), "r"(w0[4]), "r"(w0[5]), "r"(w0[6]), "r"(w0[7])
                 : "memory");
    if (has2) {
        __nv_bfloat16* b1 = g_grid + v1 * NB;
        asm volatile("red.global.add.noftz.v4.bf16x2 [%0], {%1, %2, %3, %4};"
                     :: "l"(b1), "r"(w1[0]), "r"(w1[1]), "r"(w1[2]), "r"(w1[3])
                     : "memory");
        asm volatile("red.global.add.noftz.v4.bf16x2 [%0], {%1, %2, %3, %4};"
                     :: "l"(b1 + 8), "r"(w1[4]), "r"(w1[5]), "r"(w1[6]), "r"(w1[7])
                     : "memory");
    }
}

// ---------------------------------------------------------------------------
// Packed diff-accumulate (proven r4): HADD2 diff, shl/and unpack, FADD |.|
// TV, packed fma.rn.f32x2 MSE.
// ---------------------------------------------------------------------------
#define ACCW(sw, nw, k, mp) do {                                              \
    __nv_bfloat162 _a = *reinterpret_cast<const __nv_bfloat162*>(&(nw));      \
    __nv_bfloat162 _b = *reinterpret_cast<const __nv_bfloat162*>(&(sw));      \
    __nv_bfloat162 _d = __hsub2(_a, _b);                                      \
    unsigned _du = *reinterpret_cast<unsigned*>(&_d);                         \
    float _lo = __uint_as_float(_du << 16);                                   \
    float _hi = __uint_as_float(_du & 0xffff0000u);                           \
    tv[(k)]     += fabsf(_lo);                                                \
    tv[(k) + 1] += fabsf(_hi);                                                \
    unsigned long long _dp;                                                   \
    asm("mov.b64 %0, {%1, %2};" : "=l"(_dp)                                   \
        : "r"(__float_as_uint(_lo)), "r"(__float_as_uint(_hi)));              \
    asm("fma.rn.f32x2 %0, %1, %2, %3;" : "=l"(mp)                             \
        : "l"(_dp), "l"(_dp), "l"(mp));                                       \
} while (0)

#define ACC4(s, nb) do {                                                      \
    ACCW((s).x, (nb).x, 0, msep[0]);                                          \
    ACCW((s).y, (nb).y, 2, msep[1]);                                          \
    ACCW((s).z, (nb).z, 4, msep[2]);                                          \
    ACCW((s).w, (nb).w, 6, msep[3]);                                          \
} while (0)

// ---------------------------------------------------------------------------
// Reduce (r5 proven config): grid = 16 y-octets x 32 z-quads, block = 8 warps,
// warp = one y row, 4 z-plane loop. 512B contiguous warp loads; x+1 direct
// (+2, L1 hit), y+1 via sibling warps (L1), z+1 via next zi (L1).
// ---------------------------------------------------------------------------
__global__ void reduce_kernel() {
    const uint4* __restrict__ g4 = (const uint4*)g_grid;
    int tid  = threadIdx.x;
    int lane = tid & 31;
    int wrp  = tid >> 5;             // 0..7
    int bg   = lane & 1;
    int xl   = lane >> 1;            // 0..15
    int y    = blockIdx.x * 8 + wrp; // 0..127
    bool yok = (y < XDIM - 1);

    float tv[8];
    unsigned long long msep[4];
#pragma unroll
    for (int i = 0; i < 8; i++) tv[i] = 0.f;
#pragma unroll
    for (int i = 0; i < 4; i++) msep[i] = 0ull;

    for (int zi = 0; zi < 4; zi++) {
        int z = blockIdx.y * 4 + zi;
        bool zok = (z < XDIM - 1);
        size_t row2 = ((size_t)(z << 7) + y) * (XDIM * 2);  // uint4 idx at x=0

#pragma unroll
        for (int c = 0; c < 8; c++) {
            size_t i0 = row2 + c * 32 + lane;
            uint4 s = g4[i0];

            if (c < 7) {
                uint4 nx = g4[i0 + 2];
                ACC4(s, nx);
            } else if (xl < 15) {                  // x = 112..126 only
                uint4 nx = g4[i0 + 2];
                ACC4(s, nx);
            }
            if (yok) { uint4 ny = g4[i0 + 2 * XDIM];        ACC4(s, ny); }
            if (zok) { uint4 nz = g4[i0 + 2 * XDIM * XDIM]; ACC4(s, nz); }
        }
    }

    // Unpack packed mse pairs.
    float mse[8];
#pragma unroll
    for (int i = 0; i < 4; i++) {
        unsigned _lo, _hi;
        asm("mov.b64 {%0, %1}, %2;" : "=r"(_lo), "=r"(_hi) : "l"(msep[i]));
        mse[2 * i]     = __uint_as_float(_lo);
        mse[2 * i + 1] = __uint_as_float(_hi);
    }

    // Warp reduce over lanes sharing bg (stride-2 lanes): xor 2,4,8,16.
#pragma unroll
    for (int off = 2; off <= 16; off <<= 1) {
#pragma unroll
        for (int i = 0; i < 8; i++) {
            tv[i]  += __shfl_xor_sync(0xffffffffu, tv[i],  off);
            mse[i] += __shfl_xor_sync(0xffffffffu, mse[i], off);
        }
    }

    __shared__ float s_tv[NB], s_mse[NB];
    if (tid < NB) { s_tv[tid] = 0.f; s_mse[tid] = 0.f; }
    __syncthreads();

    if (lane < 2) {                  // lane 0 = bg0 totals, lane 1 = bg1
#pragma unroll
        for (int i = 0; i < 8; i++) {
            atomicAdd(&s_tv[bg * 8 + i],  tv[i]);
            atomicAdd(&s_mse[bg * 8 + i], mse[i]);
        }
    }
    __syncthreads();

    if (tid < NB) {
        atomicAdd(&g_acc[tid],      (double)s_tv[tid]);
        atomicAdd(&g_acc[NB + tid], (double)s_mse[tid]);
    }
}

// ---------------------------------------------------------------------------
// Zero the touched voxels with one 256-bit store each (voxel = 32B, 32B
// aligned); last block finalizes (normalize g_acc -> out, reset).
// ---------------------------------------------------------------------------
__global__ void zero_fin_kernel(const int* __restrict__ idx, int N,
                                float* __restrict__ out) {
    if (blockIdx.x == gridDim.x - 1) {
        int t = threadIdx.x;
        if (t < 32) {
            double norm = (t < NB) ? (double)X3
                                   : (double)(2 * XDIM * XDIM - 2 * XDIM);
            out[t] = (float)(g_acc[t] / norm);
            g_acc[t] = 0.0;          // restore invariant for next replay
        }
        return;
    }
    int n = blockIdx.x * blockDim.x + threadIdx.x;
    if (n >= N) return;
    int z = __ldcs(idx + 3 * n + 0);
    int y = __ldcs(idx + 3 * n + 1);
    int x = __ldcs(idx + 3 * n + 2);
    ulonglong4* p =
        (ulonglong4*)(g_grid + (size_t)(((z << 7) + y) * XDIM + x) * NB);
    *p = make_ulonglong4(0ull, 0ull, 0ull, 0ull);   // STG.256: 32B = 1 voxel
}

extern "C" void kernel_launch(void* const* d_in, const int* in_sizes, int n_in,
                              void* d_out, int out_size) {
    const int*   indices = (const int*)d_in[0];
    const float* values  = (const float*)d_in[1];
    int N = in_sizes[0] / 3;        // 500000

    int pairs = (N + 1) / 2;        // 250000
    scatter_kernel<<<(pairs + 255) / 256, 256>>>(indices, values, N);
    reduce_kernel<<<dim3(16, 32), 256>>>();
    zero_fin_kernel<<<(N + 255) / 256 + 1, 256>>>(indices, N, (float*)d_out);
}